// round 2
// baseline (speedup 1.0000x reference)
#include <cuda_runtime.h>
#include <cstdint>

// Problem shape constants
// x:               [256, 30, 30, 512] f32
// pattern_indices: [256, 30, 30]      int64 in reference -> passed as int32 by harness
// spatial_pe:      [30, 30, 256]      f32
// pattern_pe:      [64, 256]          f32
// out = x + concat(spatial_pe[h,w,:], pattern_pe[idx % 64, :])

#define D_MODEL      512
#define D_HALF       256
#define HW           900          // 30*30
#define PIX_TOTAL    (256 * 900)  // 230400 pixels
#define F4_PER_PIX   (D_MODEL / 4)      // 128 float4 per pixel
#define F4_HALF      (D_HALF / 4)       // 64 float4 in each half
#define TOTAL_F4     (PIX_TOTAL * F4_PER_PIX)  // 29,491,200

__global__ void __launch_bounds__(256)
pe_add_kernel(const float4* __restrict__ x,
              const int* __restrict__ pattern_indices,   // int32 (harness downcasts int64)
              const float4* __restrict__ spatial_pe,     // [900 * 64] float4
              const float4* __restrict__ pattern_pe,     // [64 * 64] float4
              float4* __restrict__ out)
{
    int64_t i = (int64_t)blockIdx.x * blockDim.x + threadIdx.x;

    if (i >= (int64_t)TOTAL_F4) return;

    // decompose: pixel index and float4-within-pixel
    int d4  = (int)(i & (F4_PER_PIX - 1));   // 0..127
    int64_t pix = i >> 7;                    // 0..230399

    float4 xv = x[i];
    float4 pe;

    if (d4 < F4_HALF) {
        // spatial half: table indexed by (h,w) = pix % 900
        int hw = (int)(pix % HW);
        pe = spatial_pe[(int64_t)hw * F4_HALF + d4];
    } else {
        // pattern half: gather by per-pixel index
        int idx = pattern_indices[pix] & 63;
        pe = pattern_pe[(int64_t)idx * F4_HALF + (d4 - F4_HALF)];
    }

    xv.x += pe.x;
    xv.y += pe.y;
    xv.z += pe.z;
    xv.w += pe.w;
    out[i] = xv;
}

extern "C" void kernel_launch(void* const* d_in, const int* in_sizes, int n_in,
                              void* d_out, int out_size)
{
    const float4* x   = (const float4*)d_in[0];
    const int*    pid = (const int*)d_in[1];
    const float4* spe = (const float4*)d_in[2];
    const float4* ppe = (const float4*)d_in[3];
    float4*       out = (float4*)d_out;

    const int block = 256;
    int64_t total = (int64_t)TOTAL_F4;
    int grid = (int)((total + block - 1) / block);

    pe_add_kernel<<<grid, block>>>(x, pid, spe, ppe, out);
}

// round 3
// speedup vs baseline: 1.1457x; 1.1457x over previous
#include <cuda_runtime.h>
#include <cstdint>

// x:               [256, 30, 30, 512] f32   = [230400 pixels][128 float4]
// pattern_indices: [230400]           int32 (harness downcasts int64)
// spatial_pe:      [900][64]          float4
// pattern_pe:      [64][64]           float4
// out = x + concat(spatial_pe[hw], pattern_pe[idx & 63]) per pixel
//
// Layout: blockDim=128, each block handles 4 consecutive pixels.
// Thread t owns channel-float4 d4 = t for pixels pix0..pix0+3:
//   - d4 is constant per thread -> spatial/pattern branch is warp-uniform, hoisted
//   - 4 independent x loads front-batched -> MLP ~8, hides DRAM latency
//   - single %900 per thread, wrap by conditional subtract

#define HW        900
#define PIX_TOTAL (256 * 900)       // 230400
#define PIX_PER_BLOCK 4

__global__ void __launch_bounds__(128)
pe_add_kernel(const float4* __restrict__ x,
              const int*    __restrict__ pattern_indices,
              const float4* __restrict__ spatial_pe,   // [900*64]
              const float4* __restrict__ pattern_pe,   // [64*64]
              float4*       __restrict__ out)
{
    const int t    = threadIdx.x;             // 0..127 == d4
    const int pix0 = blockIdx.x * PIX_PER_BLOCK;
    const int base = pix0 * 128 + t;          // < 29.5M, fits int32

    // Front-batch the 4 streaming x loads (independent, fully coalesced:
    // each is a warp-contiguous 512B request).
    float4 xv[PIX_PER_BLOCK];
#pragma unroll
    for (int k = 0; k < PIX_PER_BLOCK; k++)
        xv[k] = x[base + k * 128];

    float4 pe[PIX_PER_BLOCK];
    if (t < 64) {
        // spatial half: hw = pixel % 900, consecutive pixels -> hw0+k with wrap
        int hw0 = pix0 % HW;
#pragma unroll
        for (int k = 0; k < PIX_PER_BLOCK; k++) {
            int hw = hw0 + k;
            if (hw >= HW) hw -= HW;
            pe[k] = spatial_pe[hw * 64 + t];
        }
    } else {
        // pattern half: per-pixel gather (index load broadcasts across the warp)
        int idx[PIX_PER_BLOCK];
#pragma unroll
        for (int k = 0; k < PIX_PER_BLOCK; k++)
            idx[k] = pattern_indices[pix0 + k] & 63;
#pragma unroll
        for (int k = 0; k < PIX_PER_BLOCK; k++)
            pe[k] = pattern_pe[idx[k] * 64 + (t - 64)];
    }

#pragma unroll
    for (int k = 0; k < PIX_PER_BLOCK; k++) {
        xv[k].x += pe[k].x;
        xv[k].y += pe[k].y;
        xv[k].z += pe[k].z;
        xv[k].w += pe[k].w;
        out[base + k * 128] = xv[k];
    }
}

extern "C" void kernel_launch(void* const* d_in, const int* in_sizes, int n_in,
                              void* d_out, int out_size)
{
    const float4* x   = (const float4*)d_in[0];
    const int*    pid = (const int*)d_in[1];
    const float4* spe = (const float4*)d_in[2];
    const float4* ppe = (const float4*)d_in[3];
    float4*       out = (float4*)d_out;

    const int grid = PIX_TOTAL / PIX_PER_BLOCK;   // 57600 blocks
    pe_add_kernel<<<grid, 128>>>(x, pid, spe, ppe, out);
}